// round 1
// baseline (speedup 1.0000x reference)
#include <cuda_runtime.h>
#include <math.h>

// Problem constants
#define BATCH 4
#define IMH 1080
#define IMW 1920
#define PLANE (IMH*IMW)          // 2073600
#define Q4 (PLANE/4)             // 518400
#define TH 256                   // thumbnail size
#define S 33
#define S3 (S*S*S)               // 35937

// Scratch (device globals; allocation is forbidden)
__device__ float g_tmpW[BATCH*3*IMH*TH];     // after W-resize  [b,c,1080,256]
__device__ float g_thumb[BATCH*3*TH*TH];     // [b,c,256,256]
__device__ float g_a1[BATCH*16*128*128];
__device__ float g_a2[BATCH*32*64*64];
__device__ float g_pooled[BATCH*32];
__device__ float g_wts[BATCH*3];
__device__ float4 g_lut[BATCH*S3];           // blended LUT, rgb + pad

// ---------------------------------------------------------------------------
// 1) separable antialiased triangle resize, W: 1920 -> 256  (inv_scale = 7.5)
// ---------------------------------------------------------------------------
__global__ void k_resize_w(const float* __restrict__ img) {
    __shared__ float srow[IMW];
    int row = blockIdx.x;                      // 0 .. 4*3*1080-1
    const float* src = img + (size_t)row * IMW;
    for (int i = threadIdx.x; i < IMW; i += 256) srow[i] = src[i];
    __syncthreads();
    int ow = threadIdx.x;                      // 256 threads = 256 out cols
    const float INV = 7.5f;
    float sf = (ow + 0.5f) * INV - 0.5f;
    int jlo = (int)ceilf(sf - INV); if (jlo < 0) jlo = 0;
    int jhi = (int)floorf(sf + INV); if (jhi > IMW-1) jhi = IMW-1;
    float acc = 0.f, wsum = 0.f;
    for (int j = jlo; j <= jhi; j++) {
        float w = 1.0f - fabsf(sf - (float)j) * (1.0f/INV);
        if (w > 0.f) { acc += w * srow[j]; wsum += w; }
    }
    g_tmpW[(size_t)row * TH + ow] = acc / wsum;
}

// H: 1080 -> 256  (inv_scale = 4.21875)
__global__ void k_resize_h() {
    int t = blockIdx.x * blockDim.x + threadIdx.x;
    if (t >= BATCH*3*TH*TH) return;
    int ow = t & 255;
    int oh = (t >> 8) & 255;
    int bc = t >> 16;
    const float INV = 4.21875f;
    float sf = (oh + 0.5f) * INV - 0.5f;
    int jlo = (int)ceilf(sf - INV); if (jlo < 0) jlo = 0;
    int jhi = (int)floorf(sf + INV); if (jhi > IMH-1) jhi = IMH-1;
    float acc = 0.f, wsum = 0.f;
    const float* col = g_tmpW + (size_t)bc * IMH * TH + ow;
    for (int j = jlo; j <= jhi; j++) {
        float w = 1.0f - fabsf(sf - (float)j) * (1.0f/INV);
        if (w > 0.f) { acc += w * col[j * TH]; wsum += w; }
    }
    g_thumb[t] = acc / wsum;
}

// ---------------------------------------------------------------------------
// 2) conv1: [b,3,256,256] -> relu -> [b,16,128,128], stride 2, SAME (pad 0/1)
//    block = (b, 32x32 output tile), 1024 threads, all 16 co in registers
// ---------------------------------------------------------------------------
__global__ __launch_bounds__(1024) void k_conv1(const float* __restrict__ w,
                                                const float* __restrict__ bias) {
    __shared__ float sIn[65*65];
    __shared__ float sW[16*3*9];
    __shared__ float sB[16];
    int blk = blockIdx.x;          // b*16 + tile
    int b = blk >> 4, tile = blk & 15;
    int oy0 = (tile >> 2) * 32, ox0 = (tile & 3) * 32;
    int tid = threadIdx.x;
    if (tid < 432) sW[tid] = w[tid];
    if (tid >= 432 && tid < 448) sB[tid-432] = bias[tid-432];
    int ly = tid >> 5, lx = tid & 31;
    int oy = oy0 + ly, ox = ox0 + lx;
    float acc[16];
    #pragma unroll
    for (int i = 0; i < 16; i++) acc[i] = 0.f;
    for (int ci = 0; ci < 3; ci++) {
        __syncthreads();
        const float* src = g_thumb + (size_t)(b*3 + ci) * TH * TH;
        for (int i = tid; i < 65*65; i += 1024) {
            int dy = i / 65, dx = i - dy*65;
            int iy = 2*oy0 + dy, ix = 2*ox0 + dx;
            sIn[i] = (iy < TH && ix < TH) ? src[iy*TH + ix] : 0.f;
        }
        __syncthreads();
        float v[9];
        #pragma unroll
        for (int kh = 0; kh < 3; kh++)
            #pragma unroll
            for (int kw = 0; kw < 3; kw++)
                v[kh*3+kw] = sIn[(2*ly + kh)*65 + 2*lx + kw];
        #pragma unroll
        for (int co = 0; co < 16; co++) {
            const float* wp = &sW[(co*3 + ci)*9];
            float a = acc[co];
            #pragma unroll
            for (int k = 0; k < 9; k++) a += v[k] * wp[k];
            acc[co] = a;
        }
    }
    #pragma unroll
    for (int co = 0; co < 16; co++) {
        float r = acc[co] + sB[co];
        r = r > 0.f ? r : 0.f;
        g_a1[(((size_t)b*16 + co)*128 + oy)*128 + ox] = r;
    }
}

// conv2: [b,16,128,128] -> relu -> [b,32,64,64]; block = (b, 16x16 tile), 256 thr
__global__ __launch_bounds__(256) void k_conv2(const float* __restrict__ w,
                                               const float* __restrict__ bias) {
    __shared__ float sIn[33*33];
    __shared__ float sW[32*16*9];   // 4608 floats
    __shared__ float sB[32];
    int blk = blockIdx.x;
    int b = blk >> 4, tile = blk & 15;
    int oy0 = (tile >> 2) * 16, ox0 = (tile & 3) * 16;
    int tid = threadIdx.x;
    for (int i = tid; i < 4608; i += 256) sW[i] = w[i];
    if (tid < 32) sB[tid] = bias[tid];
    int ly = tid >> 4, lx = tid & 15;
    int oy = oy0 + ly, ox = ox0 + lx;
    float acc[32];
    #pragma unroll
    for (int i = 0; i < 32; i++) acc[i] = 0.f;
    for (int ci = 0; ci < 16; ci++) {
        __syncthreads();
        const float* src = g_a1 + (size_t)(b*16 + ci) * 128 * 128;
        for (int i = tid; i < 33*33; i += 256) {
            int dy = i / 33, dx = i - dy*33;
            int iy = 2*oy0 + dy, ix = 2*ox0 + dx;
            sIn[i] = (iy < 128 && ix < 128) ? src[iy*128 + ix] : 0.f;
        }
        __syncthreads();
        float v[9];
        #pragma unroll
        for (int kh = 0; kh < 3; kh++)
            #pragma unroll
            for (int kw = 0; kw < 3; kw++)
                v[kh*3+kw] = sIn[(2*ly + kh)*33 + 2*lx + kw];
        #pragma unroll
        for (int co = 0; co < 32; co++) {
            const float* wp = &sW[(co*16 + ci)*9];
            float a = acc[co];
            #pragma unroll
            for (int k = 0; k < 9; k++) a += v[k] * wp[k];
            acc[co] = a;
        }
    }
    #pragma unroll
    for (int co = 0; co < 32; co++) {
        float r = acc[co] + sB[co];
        r = r > 0.f ? r : 0.f;
        g_a2[(((size_t)b*32 + co)*64 + oy)*64 + ox] = r;
    }
}

// global average pool: one block per (b,c)
__global__ void k_gap() {
    __shared__ float red[256];
    int bc = blockIdx.x;
    const float* src = g_a2 + (size_t)bc * 4096;
    float s = 0.f;
    for (int i = threadIdx.x; i < 4096; i += 256) s += src[i];
    red[threadIdx.x] = s;
    __syncthreads();
    for (int st = 128; st > 0; st >>= 1) {
        if (threadIdx.x < st) red[threadIdx.x] += red[threadIdx.x + st];
        __syncthreads();
    }
    if (threadIdx.x == 0) g_pooled[bc] = red[0] * (1.0f/4096.0f);
}

// dense + softmax -> per-batch basis weights
__global__ void k_dense(const float* __restrict__ dw, const float* __restrict__ db) {
    int b = threadIdx.x;
    if (b < BATCH) {
        float l[3];
        #pragma unroll
        for (int k = 0; k < 3; k++) {
            float a = db[k];
            for (int c = 0; c < 32; c++) a += g_pooled[b*32 + c] * dw[c*3 + k];
            l[k] = a;
        }
        float m = fmaxf(l[0], fmaxf(l[1], l[2]));
        float e0 = expf(l[0]-m), e1 = expf(l[1]-m), e2 = expf(l[2]-m);
        float s = 1.0f / (e0 + e1 + e2);
        g_wts[b*3+0] = e0*s; g_wts[b*3+1] = e1*s; g_wts[b*3+2] = e2*s;
    }
}

// blend basis LUTs -> float4 LUT per batch
__global__ void k_blend(const float* __restrict__ basis) {
    int t = blockIdx.x * blockDim.x + threadIdx.x;
    if (t >= BATCH * S3) return;
    int b = t / S3, p = t - b * S3;
    float w0 = g_wts[b*3], w1 = g_wts[b*3+1], w2 = g_wts[b*3+2];
    const float* b0 = basis + (size_t)p * 3;
    const float* b1 = b0 + (size_t)S3 * 3;
    const float* b2 = b1 + (size_t)S3 * 3;
    float r  = w0*b0[0] + w1*b1[0] + w2*b2[0];
    float g  = w0*b0[1] + w1*b1[1] + w2*b2[1];
    float bl = w0*b0[2] + w1*b1[2] + w2*b2[2];
    g_lut[t] = make_float4(r, g, bl, 0.f);
}

// ---------------------------------------------------------------------------
// 3) trilinear LUT apply; thread = 4 consecutive pixels (float4 along W)
// ---------------------------------------------------------------------------
__device__ __forceinline__ void lut_one(const float4* __restrict__ lut,
                                        float r, float g, float b,
                                        float& orr, float& org, float& orb) {
    float px = fminf(fmaxf(r, 0.f), 1.f) * 32.f;   // x <- R
    float py = fminf(fmaxf(g, 0.f), 1.f) * 32.f;   // y <- G
    float pz = fminf(fmaxf(b, 0.f), 1.f) * 32.f;   // z <- B
    int x0 = min((int)px, 31);
    int y0 = min((int)py, 31);
    int z0 = min((int)pz, 31);
    float fx = px - (float)x0, fy = py - (float)y0, fz = pz - (float)z0;
    int base = (z0*S + y0)*S + x0;
    float4 c000 = __ldg(lut + base);
    float4 c001 = __ldg(lut + base + 1);
    float4 c010 = __ldg(lut + base + S);
    float4 c011 = __ldg(lut + base + S + 1);
    float4 c100 = __ldg(lut + base + S*S);
    float4 c101 = __ldg(lut + base + S*S + 1);
    float4 c110 = __ldg(lut + base + S*S + S);
    float4 c111 = __ldg(lut + base + S*S + S + 1);
    float gx0 = 1.f - fx, gy0 = 1.f - fy, gz0 = 1.f - fz;
    float w000 = gz0*gy0*gx0, w001 = gz0*gy0*fx;
    float w010 = gz0*fy*gx0,  w011 = gz0*fy*fx;
    float w100 = fz*gy0*gx0,  w101 = fz*gy0*fx;
    float w110 = fz*fy*gx0,   w111 = fz*fy*fx;
    float vr = w000*c000.x + w001*c001.x + w010*c010.x + w011*c011.x
             + w100*c100.x + w101*c101.x + w110*c110.x + w111*c111.x;
    float vg = w000*c000.y + w001*c001.y + w010*c010.y + w011*c011.y
             + w100*c100.y + w101*c101.y + w110*c110.y + w111*c111.y;
    float vb = w000*c000.z + w001*c001.z + w010*c010.z + w011*c011.z
             + w100*c100.z + w101*c101.z + w110*c110.z + w111*c111.z;
    orr = fminf(fmaxf(vr, 0.f), 1.f);
    org = fminf(fmaxf(vg, 0.f), 1.f);
    orb = fminf(fmaxf(vb, 0.f), 1.f);
}

__global__ __launch_bounds__(256) void k_apply(const float* __restrict__ img,
                                               float* __restrict__ out) {
    int t = blockIdx.x * blockDim.x + threadIdx.x;
    if (t >= BATCH * Q4) return;
    int b = t / Q4;
    int off4 = t - b * Q4;
    const float4* pr = (const float4*)(img + (size_t)b * 3 * PLANE) + off4;
    float4 R  = __ldg(pr);
    float4 G  = __ldg(pr + Q4);
    float4 Bc = __ldg(pr + 2*Q4);
    const float4* lut = g_lut + (size_t)b * S3;
    float rr[4] = {R.x, R.y, R.z, R.w};
    float gg[4] = {G.x, G.y, G.z, G.w};
    float bb[4] = {Bc.x, Bc.y, Bc.z, Bc.w};
    float orr[4], org[4], orb[4];
    #pragma unroll
    for (int i = 0; i < 4; i++)
        lut_one(lut, rr[i], gg[i], bb[i], orr[i], org[i], orb[i]);
    float4* po = (float4*)(out + (size_t)b * 3 * PLANE) + off4;
    po[0]      = make_float4(orr[0], orr[1], orr[2], orr[3]);
    po[Q4]     = make_float4(org[0], org[1], org[2], org[3]);
    po[2*Q4]   = make_float4(orb[0], orb[1], orb[2], orb[3]);
}

// ---------------------------------------------------------------------------
extern "C" void kernel_launch(void* const* d_in, const int* in_sizes, int n_in,
                              void* d_out, int out_size) {
    const float* image   = (const float*)d_in[0];
    const float* basis   = (const float*)d_in[1];
    const float* conv1_w = (const float*)d_in[2];
    const float* conv1_b = (const float*)d_in[3];
    const float* conv2_w = (const float*)d_in[4];
    const float* conv2_b = (const float*)d_in[5];
    const float* dense_w = (const float*)d_in[6];
    const float* dense_b = (const float*)d_in[7];
    float* out = (float*)d_out;

    k_resize_w<<<BATCH*3*IMH, 256>>>(image);
    k_resize_h<<<(BATCH*3*TH*TH + 255)/256, 256>>>();
    k_conv1<<<BATCH*16, 1024>>>(conv1_w, conv1_b);
    k_conv2<<<BATCH*16, 256>>>(conv2_w, conv2_b);
    k_gap<<<BATCH*32, 256>>>();
    k_dense<<<1, 32>>>(dense_w, dense_b);
    k_blend<<<(BATCH*S3 + 255)/256, 256>>>(basis);
    k_apply<<<(BATCH*Q4 + 255)/256, 256>>>(image, out);
}

// round 6
// speedup vs baseline: 1.3360x; 1.3360x over previous
#include <cuda_runtime.h>
#include <math.h>

// Problem constants
#define BATCH 4
#define IMH 1080
#define IMW 1920
#define PLANE (IMH*IMW)          // 2073600
#define Q4 (PLANE/4)             // 518400
#define TH 256                   // thumbnail size
#define S 33
#define S3 (S*S*S)               // 35937

// Scratch (device globals; allocation is forbidden)
__device__ float g_tmpW[BATCH*3*IMH*TH];     // after W-resize  [b,c,1080,256]
__device__ float g_thumb[BATCH*3*TH*TH];     // [b,c,256,256]
__device__ float g_a1[BATCH*16*128*128];
__device__ float g_a2[BATCH*32*64*64];
__device__ float g_pooled[BATCH*32];
__device__ float g_wts[BATCH*3];
// packed LUT: entry (b,z,y,x) = {r,g,b @ x ; r,g,b @ x+1, pad, pad} fp32, 32B
struct __align__(32) LutPair { float v[8]; };
__device__ LutPair g_lutp[BATCH*S3];

// 256-bit non-coherent global load (Blackwell LDG.E.256)
__device__ __forceinline__ void ldg256(const LutPair* __restrict__ p, float* o) {
    asm volatile("ld.global.nc.v8.f32 {%0,%1,%2,%3,%4,%5,%6,%7}, [%8];"
                 : "=f"(o[0]), "=f"(o[1]), "=f"(o[2]), "=f"(o[3]),
                   "=f"(o[4]), "=f"(o[5]), "=f"(o[6]), "=f"(o[7])
                 : "l"(p));
}

// ---------------------------------------------------------------------------
// 1) separable antialiased triangle resize, W: 1920 -> 256  (inv_scale = 7.5)
// ---------------------------------------------------------------------------
__global__ void k_resize_w(const float* __restrict__ img) {
    __shared__ float srow[IMW];
    int row = blockIdx.x;                      // 0 .. 4*3*1080-1
    const float* src = img + (size_t)row * IMW;
    for (int i = threadIdx.x; i < IMW; i += 256) srow[i] = src[i];
    __syncthreads();
    int ow = threadIdx.x;
    const float INV = 7.5f;
    float sf = (ow + 0.5f) * INV - 0.5f;
    int jlo = (int)ceilf(sf - INV); if (jlo < 0) jlo = 0;
    int jhi = (int)floorf(sf + INV); if (jhi > IMW-1) jhi = IMW-1;
    float acc = 0.f, wsum = 0.f;
    for (int j = jlo; j <= jhi; j++) {
        float w = 1.0f - fabsf(sf - (float)j) * (1.0f/INV);
        if (w > 0.f) { acc += w * srow[j]; wsum += w; }
    }
    g_tmpW[(size_t)row * TH + ow] = acc / wsum;
}

// H: 1080 -> 256  (inv_scale = 4.21875)
__global__ void k_resize_h() {
    int t = blockIdx.x * blockDim.x + threadIdx.x;
    if (t >= BATCH*3*TH*TH) return;
    int ow = t & 255;
    int oh = (t >> 8) & 255;
    int bc = t >> 16;
    const float INV = 4.21875f;
    float sf = (oh + 0.5f) * INV - 0.5f;
    int jlo = (int)ceilf(sf - INV); if (jlo < 0) jlo = 0;
    int jhi = (int)floorf(sf + INV); if (jhi > IMH-1) jhi = IMH-1;
    float acc = 0.f, wsum = 0.f;
    const float* col = g_tmpW + (size_t)bc * IMH * TH + ow;
    for (int j = jlo; j <= jhi; j++) {
        float w = 1.0f - fabsf(sf - (float)j) * (1.0f/INV);
        if (w > 0.f) { acc += w * col[j * TH]; wsum += w; }
    }
    g_thumb[t] = acc / wsum;
}

// ---------------------------------------------------------------------------
// 2) conv1: [b,3,256,256] -> relu -> [b,16,128,128], stride 2, pad (0,1)
//    grid = B*64 (16x16 output tiles), 256 threads, 16 co per thread
// ---------------------------------------------------------------------------
__global__ __launch_bounds__(256) void k_conv1(const float* __restrict__ w,
                                               const float* __restrict__ bias) {
    __shared__ float sIn[3*33*33];   // 3267
    __shared__ float sW[16*3*9];     // 432
    __shared__ float sB[16];
    int blk = blockIdx.x;
    int b = blk >> 6, tile = blk & 63;
    int oy0 = (tile >> 3) * 16, ox0 = (tile & 7) * 16;
    int tid = threadIdx.x;
    // FIXED: stage all 432 weights with a strided loop (256 threads!), bias with tid<16
    for (int i = tid; i < 432; i += 256) sW[i] = w[i];
    if (tid < 16) sB[tid] = bias[tid];
    const float* src = g_thumb + (size_t)b * 3 * TH * TH;
    for (int i = tid; i < 3*33*33; i += 256) {
        int ci = i / 1089, r = i - ci*1089;
        int dy = r / 33, dx = r - dy*33;
        int iy = 2*oy0 + dy, ix = 2*ox0 + dx;
        sIn[i] = (iy < TH && ix < TH) ? src[(size_t)ci*TH*TH + iy*TH + ix] : 0.f;
    }
    __syncthreads();
    int ly = tid >> 4, lx = tid & 15;
    int oy = oy0 + ly, ox = ox0 + lx;
    float acc[16];
    #pragma unroll
    for (int i = 0; i < 16; i++) acc[i] = 0.f;
    #pragma unroll
    for (int ci = 0; ci < 3; ci++) {
        float v[9];
        #pragma unroll
        for (int kh = 0; kh < 3; kh++)
            #pragma unroll
            for (int kw = 0; kw < 3; kw++)
                v[kh*3+kw] = sIn[ci*1089 + (2*ly + kh)*33 + 2*lx + kw];
        #pragma unroll
        for (int co = 0; co < 16; co++) {
            const float* wp = &sW[(co*3 + ci)*9];
            float a = acc[co];
            #pragma unroll
            for (int k = 0; k < 9; k++) a += v[k] * wp[k];
            acc[co] = a;
        }
    }
    #pragma unroll
    for (int co = 0; co < 16; co++) {
        float r = acc[co] + sB[co];
        r = r > 0.f ? r : 0.f;
        g_a1[(((size_t)b*16 + co)*128 + oy)*128 + ox] = r;
    }
}

// conv2: [b,16,128,128] -> relu -> [b,32,64,64]
// grid = B*64 (8x8 output tiles), 256 threads = 64 spatial x 4 co-groups of 8
__global__ __launch_bounds__(256) void k_conv2(const float* __restrict__ w,
                                               const float* __restrict__ bias) {
    __shared__ float sIn[16*17*17];  // 4624
    __shared__ float sW[32*16*9];    // 4608
    __shared__ float sB[32];
    int blk = blockIdx.x;
    int b = blk >> 6, tile = blk & 63;
    int oy0 = (tile >> 3) * 8, ox0 = (tile & 7) * 8;
    int tid = threadIdx.x;
    for (int i = tid; i < 4608; i += 256) sW[i] = w[i];
    if (tid < 32) sB[tid] = bias[tid];
    const float* src = g_a1 + (size_t)b * 16 * 128 * 128;
    for (int i = tid; i < 16*289; i += 256) {
        int ci = i / 289, r = i - ci*289;
        int dy = r / 17, dx = r - dy*17;
        int iy = 2*oy0 + dy, ix = 2*ox0 + dx;
        sIn[i] = (iy < 128 && ix < 128) ? src[(size_t)ci*128*128 + iy*128 + ix] : 0.f;
    }
    __syncthreads();
    int sp = tid & 63, cog = tid >> 6;      // 4 co-groups of 8
    int ly = sp >> 3, lx = sp & 7;
    int oy = oy0 + ly, ox = ox0 + lx;
    float acc[8];
    #pragma unroll
    for (int i = 0; i < 8; i++) acc[i] = 0.f;
    #pragma unroll 4
    for (int ci = 0; ci < 16; ci++) {
        float v[9];
        #pragma unroll
        for (int kh = 0; kh < 3; kh++)
            #pragma unroll
            for (int kw = 0; kw < 3; kw++)
                v[kh*3+kw] = sIn[ci*289 + (2*ly + kh)*17 + 2*lx + kw];
        #pragma unroll
        for (int i = 0; i < 8; i++) {
            int co = cog*8 + i;
            const float* wp = &sW[(co*16 + ci)*9];
            float a = acc[i];
            #pragma unroll
            for (int k = 0; k < 9; k++) a += v[k] * wp[k];
            acc[i] = a;
        }
    }
    #pragma unroll
    for (int i = 0; i < 8; i++) {
        int co = cog*8 + i;
        float r = acc[i] + sB[co];
        r = r > 0.f ? r : 0.f;
        g_a2[(((size_t)b*32 + co)*64 + oy)*64 + ox] = r;
    }
}

// global average pool: one block per (b,c)
__global__ void k_gap() {
    __shared__ float red[256];
    int bc = blockIdx.x;
    const float* src = g_a2 + (size_t)bc * 4096;
    float s = 0.f;
    for (int i = threadIdx.x; i < 4096; i += 256) s += src[i];
    red[threadIdx.x] = s;
    __syncthreads();
    for (int st = 128; st > 0; st >>= 1) {
        if (threadIdx.x < st) red[threadIdx.x] += red[threadIdx.x + st];
        __syncthreads();
    }
    if (threadIdx.x == 0) g_pooled[bc] = red[0] * (1.0f/4096.0f);
}

// dense + softmax -> per-batch basis weights
__global__ void k_dense(const float* __restrict__ dw, const float* __restrict__ db) {
    int b = threadIdx.x;
    if (b < BATCH) {
        float l[3];
        #pragma unroll
        for (int k = 0; k < 3; k++) {
            float a = db[k];
            for (int c = 0; c < 32; c++) a += g_pooled[b*32 + c] * dw[c*3 + k];
            l[k] = a;
        }
        float m = fmaxf(l[0], fmaxf(l[1], l[2]));
        float e0 = expf(l[0]-m), e1 = expf(l[1]-m), e2 = expf(l[2]-m);
        float s = 1.0f / (e0 + e1 + e2);
        g_wts[b*3+0] = e0*s; g_wts[b*3+1] = e1*s; g_wts[b*3+2] = e2*s;
    }
}

// blend basis LUTs -> packed fp32 x-pair LUT per batch
__global__ void k_blend(const float* __restrict__ basis) {
    int t = blockIdx.x * blockDim.x + threadIdx.x;
    if (t >= BATCH * S3) return;
    int b = t / S3, p = t - b * S3;
    int x = p % S;
    int p1 = (x < S-1) ? p + 1 : p;       // x=32 never used as a base cell
    float w0 = g_wts[b*3], w1 = g_wts[b*3+1], w2 = g_wts[b*3+2];
    const float* a0 = basis + (size_t)p * 3;
    const float* a1 = a0 + (size_t)S3 * 3;
    const float* a2 = a1 + (size_t)S3 * 3;
    const float* c0 = basis + (size_t)p1 * 3;
    const float* c1 = c0 + (size_t)S3 * 3;
    const float* c2 = c1 + (size_t)S3 * 3;
    LutPair o;
    o.v[0] = w0*a0[0] + w1*a1[0] + w2*a2[0];
    o.v[1] = w0*a0[1] + w1*a1[1] + w2*a2[1];
    o.v[2] = w0*a0[2] + w1*a1[2] + w2*a2[2];
    o.v[3] = w0*c0[0] + w1*c1[0] + w2*c2[0];
    o.v[4] = w0*c0[1] + w1*c1[1] + w2*c2[1];
    o.v[5] = w0*c0[2] + w1*c1[2] + w2*c2[2];
    o.v[6] = 0.f; o.v[7] = 0.f;
    g_lutp[t] = o;
}

// ---------------------------------------------------------------------------
// 3) trilinear LUT apply; thread = 4 consecutive pixels (float4 along W)
//    4 x 256-bit gathers per pixel (x-pair packed in each 32B entry)
// ---------------------------------------------------------------------------
__device__ __forceinline__ void lut_one(const LutPair* __restrict__ lut,
                                        float r, float g, float b,
                                        float& orr, float& org, float& orb) {
    float px = fminf(fmaxf(r, 0.f), 1.f) * 32.f;   // x <- R
    float py = fminf(fmaxf(g, 0.f), 1.f) * 32.f;   // y <- G
    float pz = fminf(fmaxf(b, 0.f), 1.f) * 32.f;   // z <- B
    int x0 = min((int)px, 31);
    int y0 = min((int)py, 31);
    int z0 = min((int)pz, 31);
    float fx = px - (float)x0, fy = py - (float)y0, fz = pz - (float)z0;
    int base = (z0*S + y0)*S + x0;
    float e00[8], e01[8], e10[8], e11[8];
    ldg256(lut + base,           e00);   // z0,y0
    ldg256(lut + base + S,       e01);   // z0,y1
    ldg256(lut + base + S*S,     e10);   // z1,y0
    ldg256(lut + base + S*S + S, e11);   // z1,y1
    // x-lerp each
    float v00r = e00[0] + fx*(e00[3]-e00[0]), v00g = e00[1] + fx*(e00[4]-e00[1]), v00b = e00[2] + fx*(e00[5]-e00[2]);
    float v01r = e01[0] + fx*(e01[3]-e01[0]), v01g = e01[1] + fx*(e01[4]-e01[1]), v01b = e01[2] + fx*(e01[5]-e01[2]);
    float v10r = e10[0] + fx*(e10[3]-e10[0]), v10g = e10[1] + fx*(e10[4]-e10[1]), v10b = e10[2] + fx*(e10[5]-e10[2]);
    float v11r = e11[0] + fx*(e11[3]-e11[0]), v11g = e11[1] + fx*(e11[4]-e11[1]), v11b = e11[2] + fx*(e11[5]-e11[2]);
    float gy0 = 1.f - fy, gz0 = 1.f - fz;
    float vr = gz0*(gy0*v00r + fy*v01r) + fz*(gy0*v10r + fy*v11r);
    float vg = gz0*(gy0*v00g + fy*v01g) + fz*(gy0*v10g + fy*v11g);
    float vb = gz0*(gy0*v00b + fy*v01b) + fz*(gy0*v10b + fy*v11b);
    orr = fminf(fmaxf(vr, 0.f), 1.f);
    org = fminf(fmaxf(vg, 0.f), 1.f);
    orb = fminf(fmaxf(vb, 0.f), 1.f);
}

__global__ __launch_bounds__(256) void k_apply(const float* __restrict__ img,
                                               float* __restrict__ out) {
    int t = blockIdx.x * blockDim.x + threadIdx.x;
    if (t >= BATCH * Q4) return;
    int b = t / Q4;
    int off4 = t - b * Q4;
    const float4* pr = (const float4*)(img + (size_t)b * 3 * PLANE) + off4;
    float4 R  = __ldg(pr);
    float4 G  = __ldg(pr + Q4);
    float4 Bc = __ldg(pr + 2*Q4);
    const LutPair* lut = g_lutp + (size_t)b * S3;
    float rr[4] = {R.x, R.y, R.z, R.w};
    float gg[4] = {G.x, G.y, G.z, G.w};
    float bb[4] = {Bc.x, Bc.y, Bc.z, Bc.w};
    float orr[4], org[4], orb[4];
    #pragma unroll
    for (int i = 0; i < 4; i++)
        lut_one(lut, rr[i], gg[i], bb[i], orr[i], org[i], orb[i]);
    float4* po = (float4*)(out + (size_t)b * 3 * PLANE) + off4;
    po[0]      = make_float4(orr[0], orr[1], orr[2], orr[3]);
    po[Q4]     = make_float4(org[0], org[1], org[2], org[3]);
    po[2*Q4]   = make_float4(orb[0], orb[1], orb[2], orb[3]);
}

// ---------------------------------------------------------------------------
extern "C" void kernel_launch(void* const* d_in, const int* in_sizes, int n_in,
                              void* d_out, int out_size) {
    const float* image   = (const float*)d_in[0];
    const float* basis   = (const float*)d_in[1];
    const float* conv1_w = (const float*)d_in[2];
    const float* conv1_b = (const float*)d_in[3];
    const float* conv2_w = (const float*)d_in[4];
    const float* conv2_b = (const float*)d_in[5];
    const float* dense_w = (const float*)d_in[6];
    const float* dense_b = (const float*)d_in[7];
    float* out = (float*)d_out;

    k_resize_w<<<BATCH*3*IMH, 256>>>(image);
    k_resize_h<<<(BATCH*3*TH*TH + 255)/256, 256>>>();
    k_conv1<<<BATCH*64, 256>>>(conv1_w, conv1_b);
    k_conv2<<<BATCH*64, 256>>>(conv2_w, conv2_b);
    k_gap<<<BATCH*32, 256>>>();
    k_dense<<<1, 32>>>(dense_w, dense_b);
    k_blend<<<(BATCH*S3 + 255)/256, 256>>>(basis);
    k_apply<<<(BATCH*Q4 + 255)/256, 256>>>(image, out);
}

// round 9
// speedup vs baseline: 1.6837x; 1.2603x over previous
#include <cuda_runtime.h>
#include <cuda_fp16.h>
#include <math.h>

// Problem constants
#define BATCH 4
#define IMH 1080
#define IMW 1920
#define PLANE (IMH*IMW)          // 2073600
#define Q4 (PLANE/4)             // 518400
#define TH 256                   // thumbnail size
#define S 33
#define S3 (S*S*S)               // 35937

// Scratch (device globals; allocation is forbidden)
__device__ float g_tmpW[BATCH*3*IMH*TH];     // after W-resize  [b,c,1080,256]
__device__ float g_thumb[BATCH*3*TH*TH];     // [b,c,256,256]
__device__ float g_a1[BATCH*16*128*128];
__device__ float g_a2[BATCH*32*64*64];
__device__ float g_pooled[BATCH*32];
__device__ float g_wts[BATCH*3];
// packed LUT: entry (b,z,y,x) = fp16 {rgb@(x,y), rgb@(x+1,y), rgb@(x,y+1), rgb@(x+1,y+1)}
// 12 halves used of 16 -> 32B, one LDG.256 per z-plane cell quad
struct __align__(32) LutQuad { unsigned int u[8]; };
__device__ LutQuad g_lutq[BATCH*S3];

// 256-bit non-coherent global load (Blackwell LDG.E.256), raw b32
__device__ __forceinline__ void ldg256u(const LutQuad* __restrict__ p, unsigned int* o) {
    asm volatile("ld.global.nc.v8.b32 {%0,%1,%2,%3,%4,%5,%6,%7}, [%8];"
                 : "=r"(o[0]), "=r"(o[1]), "=r"(o[2]), "=r"(o[3]),
                   "=r"(o[4]), "=r"(o[5]), "=r"(o[6]), "=r"(o[7])
                 : "l"(p));
}

// ---------------------------------------------------------------------------
// 1) separable antialiased triangle resize, W: 1920 -> 256  (inv_scale = 7.5)
// ---------------------------------------------------------------------------
__global__ void k_resize_w(const float* __restrict__ img) {
    __shared__ float srow[IMW];
    int row = blockIdx.x;                      // 0 .. 4*3*1080-1
    const float* src = img + (size_t)row * IMW;
    for (int i = threadIdx.x; i < IMW; i += 256) srow[i] = src[i];
    __syncthreads();
    int ow = threadIdx.x;
    const float INV = 7.5f;
    float sf = (ow + 0.5f) * INV - 0.5f;
    int jlo = (int)ceilf(sf - INV); if (jlo < 0) jlo = 0;
    int jhi = (int)floorf(sf + INV); if (jhi > IMW-1) jhi = IMW-1;
    float acc = 0.f, wsum = 0.f;
    for (int j = jlo; j <= jhi; j++) {
        float w = 1.0f - fabsf(sf - (float)j) * (1.0f/INV);
        if (w > 0.f) { acc += w * srow[j]; wsum += w; }
    }
    g_tmpW[(size_t)row * TH + ow] = acc / wsum;
}

// H: 1080 -> 256  (inv_scale = 4.21875)
__global__ void k_resize_h() {
    int t = blockIdx.x * blockDim.x + threadIdx.x;
    if (t >= BATCH*3*TH*TH) return;
    int ow = t & 255;
    int oh = (t >> 8) & 255;
    int bc = t >> 16;
    const float INV = 4.21875f;
    float sf = (oh + 0.5f) * INV - 0.5f;
    int jlo = (int)ceilf(sf - INV); if (jlo < 0) jlo = 0;
    int jhi = (int)floorf(sf + INV); if (jhi > IMH-1) jhi = IMH-1;
    float acc = 0.f, wsum = 0.f;
    const float* col = g_tmpW + (size_t)bc * IMH * TH + ow;
    for (int j = jlo; j <= jhi; j++) {
        float w = 1.0f - fabsf(sf - (float)j) * (1.0f/INV);
        if (w > 0.f) { acc += w * col[j * TH]; wsum += w; }
    }
    g_thumb[t] = acc / wsum;
}

// ---------------------------------------------------------------------------
// 2) conv1: [b,3,256,256] -> relu -> [b,16,128,128], stride 2, pad (0,1)
//    grid = B*64 (16x16 output tiles), 256 threads, 16 co per thread
//    weights padded to 12/group for LDS.128
// ---------------------------------------------------------------------------
__global__ __launch_bounds__(256) void k_conv1(const float* __restrict__ w,
                                               const float* __restrict__ bias) {
    __shared__ float sIn[3*33*33];   // 3267
    __shared__ float sW[48*12];      // (co*3+ci) groups padded to 12
    __shared__ float sB[16];
    int blk = blockIdx.x;
    int b = blk >> 6, tile = blk & 63;
    int oy0 = (tile >> 3) * 16, ox0 = (tile & 7) * 16;
    int tid = threadIdx.x;
    for (int i = tid; i < 432; i += 256) { int grp = i/9, k = i - grp*9; sW[grp*12 + k] = w[i]; }
    if (tid < 16) sB[tid] = bias[tid];
    const float* src = g_thumb + (size_t)b * 3 * TH * TH;
    for (int i = tid; i < 3*33*33; i += 256) {
        int ci = i / 1089, r = i - ci*1089;
        int dy = r / 33, dx = r - dy*33;
        int iy = 2*oy0 + dy, ix = 2*ox0 + dx;
        sIn[i] = (iy < TH && ix < TH) ? src[(size_t)ci*TH*TH + iy*TH + ix] : 0.f;
    }
    __syncthreads();
    int ly = tid >> 4, lx = tid & 15;
    int oy = oy0 + ly, ox = ox0 + lx;
    float acc[16];
    #pragma unroll
    for (int i = 0; i < 16; i++) acc[i] = 0.f;
    #pragma unroll
    for (int ci = 0; ci < 3; ci++) {
        float v[9];
        #pragma unroll
        for (int kh = 0; kh < 3; kh++)
            #pragma unroll
            for (int kw = 0; kw < 3; kw++)
                v[kh*3+kw] = sIn[ci*1089 + (2*ly + kh)*33 + 2*lx + kw];
        #pragma unroll
        for (int co = 0; co < 16; co++) {
            const float4* wp = (const float4*)&sW[(co*3 + ci)*12];
            float4 wa = wp[0], wb = wp[1], wc = wp[2];
            float a = acc[co];
            a += v[0]*wa.x + v[1]*wa.y + v[2]*wa.z + v[3]*wa.w;
            a += v[4]*wb.x + v[5]*wb.y + v[6]*wb.z + v[7]*wb.w;
            a += v[8]*wc.x;
            acc[co] = a;
        }
    }
    #pragma unroll
    for (int co = 0; co < 16; co++) {
        float r = acc[co] + sB[co];
        r = r > 0.f ? r : 0.f;
        g_a1[(((size_t)b*16 + co)*128 + oy)*128 + ox] = r;
    }
}

// conv2: [b,16,128,128] -> relu -> [b,32,64,64]
// grid = B*64 (8x8 output tiles), 256 threads = 64 spatial x 4 co-groups of 8
__global__ __launch_bounds__(256) void k_conv2(const float* __restrict__ w,
                                               const float* __restrict__ bias) {
    __shared__ float sIn[16*17*17];  // 4624
    __shared__ float sW[512*12];     // (co*16+ci) groups padded to 12 -> 6144 floats
    __shared__ float sB[32];
    int blk = blockIdx.x;
    int b = blk >> 6, tile = blk & 63;
    int oy0 = (tile >> 3) * 8, ox0 = (tile & 7) * 8;
    int tid = threadIdx.x;
    for (int i = tid; i < 4608; i += 256) { int grp = i/9, k = i - grp*9; sW[grp*12 + k] = w[i]; }
    if (tid < 32) sB[tid] = bias[tid];
    const float* src = g_a1 + (size_t)b * 16 * 128 * 128;
    for (int i = tid; i < 16*289; i += 256) {
        int ci = i / 289, r = i - ci*289;
        int dy = r / 17, dx = r - dy*17;
        int iy = 2*oy0 + dy, ix = 2*ox0 + dx;
        sIn[i] = (iy < 128 && ix < 128) ? src[(size_t)ci*128*128 + iy*128 + ix] : 0.f;
    }
    __syncthreads();
    int sp = tid & 63, cog = tid >> 6;      // 4 co-groups of 8
    int ly = sp >> 3, lx = sp & 7;
    int oy = oy0 + ly, ox = ox0 + lx;
    float acc[8];
    #pragma unroll
    for (int i = 0; i < 8; i++) acc[i] = 0.f;
    #pragma unroll 4
    for (int ci = 0; ci < 16; ci++) {
        float v[9];
        #pragma unroll
        for (int kh = 0; kh < 3; kh++)
            #pragma unroll
            for (int kw = 0; kw < 3; kw++)
                v[kh*3+kw] = sIn[ci*289 + (2*ly + kh)*17 + 2*lx + kw];
        #pragma unroll
        for (int i = 0; i < 8; i++) {
            int co = cog*8 + i;
            const float4* wp = (const float4*)&sW[(co*16 + ci)*12];
            float4 wa = wp[0], wb = wp[1], wc = wp[2];
            float a = acc[i];
            a += v[0]*wa.x + v[1]*wa.y + v[2]*wa.z + v[3]*wa.w;
            a += v[4]*wb.x + v[5]*wb.y + v[6]*wb.z + v[7]*wb.w;
            a += v[8]*wc.x;
            acc[i] = a;
        }
    }
    #pragma unroll
    for (int i = 0; i < 8; i++) {
        int co = cog*8 + i;
        float r = acc[i] + sB[co];
        r = r > 0.f ? r : 0.f;
        g_a2[(((size_t)b*32 + co)*64 + oy)*64 + ox] = r;
    }
}

// global average pool: one block per (b,c)
__global__ void k_gap() {
    __shared__ float red[256];
    int bc = blockIdx.x;
    const float* src = g_a2 + (size_t)bc * 4096;
    float s = 0.f;
    for (int i = threadIdx.x; i < 4096; i += 256) s += src[i];
    red[threadIdx.x] = s;
    __syncthreads();
    for (int st = 128; st > 0; st >>= 1) {
        if (threadIdx.x < st) red[threadIdx.x] += red[threadIdx.x + st];
        __syncthreads();
    }
    if (threadIdx.x == 0) g_pooled[bc] = red[0] * (1.0f/4096.0f);
}

// dense + softmax -> per-batch basis weights
__global__ void k_dense(const float* __restrict__ dw, const float* __restrict__ db) {
    int b = threadIdx.x;
    if (b < BATCH) {
        float l[3];
        #pragma unroll
        for (int k = 0; k < 3; k++) {
            float a = db[k];
            for (int c = 0; c < 32; c++) a += g_pooled[b*32 + c] * dw[c*3 + k];
            l[k] = a;
        }
        float m = fmaxf(l[0], fmaxf(l[1], l[2]));
        float e0 = expf(l[0]-m), e1 = expf(l[1]-m), e2 = expf(l[2]-m);
        float s = 1.0f / (e0 + e1 + e2);
        g_wts[b*3+0] = e0*s; g_wts[b*3+1] = e1*s; g_wts[b*3+2] = e2*s;
    }
}

// blend basis LUTs -> fp16 xy-quad LUT per batch
__device__ __forceinline__ float3 blend3(const float* __restrict__ basis,
                                         float w0, float w1, float w2, int p) {
    const float* a0 = basis + (size_t)p * 3;
    const float* a1 = a0 + (size_t)S3 * 3;
    const float* a2 = a1 + (size_t)S3 * 3;
    return make_float3(w0*a0[0] + w1*a1[0] + w2*a2[0],
                       w0*a0[1] + w1*a1[1] + w2*a2[1],
                       w0*a0[2] + w1*a1[2] + w2*a2[2]);
}

__global__ void k_blend(const float* __restrict__ basis) {
    int t = blockIdx.x * blockDim.x + threadIdx.x;
    if (t >= BATCH * S3) return;
    int b = t / S3, p = t - b * S3;
    int x = p % S;
    int y = (p / S) % S;
    int dx = (x < S-1) ? 1 : 0;
    int dy = (y < S-1) ? S : 0;
    float w0 = g_wts[b*3], w1 = g_wts[b*3+1], w2 = g_wts[b*3+2];
    float3 c00 = blend3(basis, w0, w1, w2, p);
    float3 c10 = blend3(basis, w0, w1, w2, p + dx);
    float3 c01 = blend3(basis, w0, w1, w2, p + dy);
    float3 c11 = blend3(basis, w0, w1, w2, p + dy + dx);
    __half2 h0 = __floats2half2_rn(c00.x, c00.y);
    __half2 h1 = __floats2half2_rn(c00.z, c10.x);
    __half2 h2 = __floats2half2_rn(c10.y, c10.z);
    __half2 h3 = __floats2half2_rn(c01.x, c01.y);
    __half2 h4 = __floats2half2_rn(c01.z, c11.x);
    __half2 h5 = __floats2half2_rn(c11.y, c11.z);
    LutQuad o;
    o.u[0] = *(unsigned int*)&h0;
    o.u[1] = *(unsigned int*)&h1;
    o.u[2] = *(unsigned int*)&h2;
    o.u[3] = *(unsigned int*)&h3;
    o.u[4] = *(unsigned int*)&h4;
    o.u[5] = *(unsigned int*)&h5;
    o.u[6] = 0u; o.u[7] = 0u;
    g_lutq[t] = o;
}

// ---------------------------------------------------------------------------
// 3) trilinear LUT apply; 2 x LDG.256 gathers per pixel (xy-quad per z-level)
// ---------------------------------------------------------------------------
__device__ __forceinline__ float3 quad_bilerp(const unsigned int* u, float fx, float fy) {
    float2 f0 = __half22float2(*(const __half2*)&u[0]);  // r00 g00
    float2 f1 = __half22float2(*(const __half2*)&u[1]);  // b00 r10
    float2 f2 = __half22float2(*(const __half2*)&u[2]);  // g10 b10
    float2 f3 = __half22float2(*(const __half2*)&u[3]);  // r01 g01
    float2 f4 = __half22float2(*(const __half2*)&u[4]);  // b01 r11
    float2 f5 = __half22float2(*(const __half2*)&u[5]);  // g11 b11
    float gx = 1.f - fx, gy = 1.f - fy;
    float w00 = gy*gx, w10 = gy*fx, w01 = fy*gx, w11 = fy*fx;
    return make_float3(w00*f0.x + w10*f1.y + w01*f3.x + w11*f4.y,
                       w00*f0.y + w10*f2.x + w01*f3.y + w11*f5.x,
                       w00*f1.x + w10*f2.y + w01*f4.x + w11*f5.y);
}

__device__ __forceinline__ void lut_one(const LutQuad* __restrict__ lut,
                                        float r, float g, float b,
                                        float& orr, float& org, float& orb) {
    float px = fminf(fmaxf(r, 0.f), 1.f) * 32.f;   // x <- R
    float py = fminf(fmaxf(g, 0.f), 1.f) * 32.f;   // y <- G
    float pz = fminf(fmaxf(b, 0.f), 1.f) * 32.f;   // z <- B
    int x0 = min((int)px, 31);
    int y0 = min((int)py, 31);
    int z0 = min((int)pz, 31);
    float fx = px - (float)x0, fy = py - (float)y0, fz = pz - (float)z0;
    int base = (z0*S + y0)*S + x0;
    unsigned int q0[8], q1[8];
    ldg256u(lut + base,       q0);   // z0 plane quad
    ldg256u(lut + base + S*S, q1);   // z1 plane quad
    float3 v0 = quad_bilerp(q0, fx, fy);
    float3 v1 = quad_bilerp(q1, fx, fy);
    float gz = 1.f - fz;
    orr = fminf(fmaxf(gz*v0.x + fz*v1.x, 0.f), 1.f);
    org = fminf(fmaxf(gz*v0.y + fz*v1.y, 0.f), 1.f);
    orb = fminf(fmaxf(gz*v0.z + fz*v1.z, 0.f), 1.f);
}

__global__ __launch_bounds__(256) void k_apply(const float* __restrict__ img,
                                               float* __restrict__ out) {
    int t = blockIdx.x * blockDim.x + threadIdx.x;
    if (t >= BATCH * Q4) return;
    int b = t / Q4;
    int off4 = t - b * Q4;
    const float4* pr = (const float4*)(img + (size_t)b * 3 * PLANE) + off4;
    float4 R  = __ldg(pr);
    float4 G  = __ldg(pr + Q4);
    float4 Bc = __ldg(pr + 2*Q4);
    const LutQuad* lut = g_lutq + (size_t)b * S3;
    float rr[4] = {R.x, R.y, R.z, R.w};
    float gg[4] = {G.x, G.y, G.z, G.w};
    float bb[4] = {Bc.x, Bc.y, Bc.z, Bc.w};
    float orr[4], org[4], orb[4];
    #pragma unroll
    for (int i = 0; i < 4; i++)
        lut_one(lut, rr[i], gg[i], bb[i], orr[i], org[i], orb[i]);
    float4* po = (float4*)(out + (size_t)b * 3 * PLANE) + off4;
    po[0]      = make_float4(orr[0], orr[1], orr[2], orr[3]);
    po[Q4]     = make_float4(org[0], org[1], org[2], org[3]);
    po[2*Q4]   = make_float4(orb[0], orb[1], orb[2], orb[3]);
}

// ---------------------------------------------------------------------------
extern "C" void kernel_launch(void* const* d_in, const int* in_sizes, int n_in,
                              void* d_out, int out_size) {
    const float* image   = (const float*)d_in[0];
    const float* basis   = (const float*)d_in[1];
    const float* conv1_w = (const float*)d_in[2];
    const float* conv1_b = (const float*)d_in[3];
    const float* conv2_w = (const float*)d_in[4];
    const float* conv2_b = (const float*)d_in[5];
    const float* dense_w = (const float*)d_in[6];
    const float* dense_b = (const float*)d_in[7];
    float* out = (float*)d_out;

    k_resize_w<<<BATCH*3*IMH, 256>>>(image);
    k_resize_h<<<(BATCH*3*TH*TH + 255)/256, 256>>>();
    k_conv1<<<BATCH*64, 256>>>(conv1_w, conv1_b);
    k_conv2<<<BATCH*64, 256>>>(conv2_w, conv2_b);
    k_gap<<<BATCH*32, 256>>>();
    k_dense<<<1, 32>>>(dense_w, dense_b);
    k_blend<<<(BATCH*S3 + 255)/256, 256>>>(basis);
    k_apply<<<(BATCH*Q4 + 255)/256, 256>>>(image, out);
}